// round 11
// baseline (speedup 1.0000x reference)
#include <cuda_runtime.h>
#include <cstdint>

#define BATCH 16384
#define D     1024
#define LN_EPS 1e-5f
#define GSPLIT 8          // split-K for G = x^T x
#define HSPLIT 4          // split-K for hebb = Wf * G

// ---------------- scratch (static device globals; no runtime alloc) ----------
__device__ __align__(16) float g_xc  [(size_t)BATCH * D];     // x rounded to tf32
__device__ __align__(16) float g_xT  [(size_t)D * BATCH];     // x^T, tf32-rounded
__device__ __align__(16) float g_wsc [(size_t)D * D];         // W_slow rounded
__device__ __align__(16) float g_wfc [(size_t)D * D];         // W_fast rounded
__device__ __align__(16) float g_fast[(size_t)BATCH * D];     // fast, fp32
__device__ __align__(16) float g_part[(size_t)GSPLIT * D * D];// split-K partials (G, then hebb)
__device__ __align__(16) float g_G   [(size_t)D * D];         // G = x^T x (full, tf32)
__device__ float g_msq_part[64 * D];
__device__ float g_msq[D];
__device__ float g_efflr[1];

// ---------------- helpers ----------------------------------------------------
__device__ __forceinline__ unsigned tf32u(float x) {
    unsigned r;
    asm("cvt.rna.tf32.f32 %0, %1;" : "=r"(r) : "f"(x));
    return r;
}
__device__ __forceinline__ unsigned fu(float x) { return __float_as_uint(x); }

__device__ __forceinline__ void mma8(float c[4],
                                     unsigned a0, unsigned a1, unsigned a2, unsigned a3,
                                     unsigned b0, unsigned b1) {
    asm volatile(
        "mma.sync.aligned.m16n8k8.row.col.f32.tf32.tf32.f32 "
        "{%0,%1,%2,%3}, {%4,%5,%6,%7}, {%8,%9}, {%0,%1,%2,%3};\n"
        : "+f"(c[0]), "+f"(c[1]), "+f"(c[2]), "+f"(c[3])
        : "r"(a0), "r"(a1), "r"(a2), "r"(a3), "r"(b0), "r"(b1));
}

__device__ __forceinline__ void cpa16(void* dst, const void* src) {
    unsigned sd = (unsigned)__cvta_generic_to_shared(dst);
    asm volatile("cp.async.cg.shared.global [%0], [%1], 16;\n" :: "r"(sd), "l"(src));
}
#define CP_COMMIT() asm volatile("cp.async.commit_group;\n" ::: "memory")
#define CP_WAIT0()  asm volatile("cp.async.wait_group 0;\n" ::: "memory")
#define CP_WAIT1()  asm volatile("cp.async.wait_group 1;\n" ::: "memory")

__device__ __forceinline__ float warpSum(float v) {
    #pragma unroll
    for (int o = 16; o > 0; o >>= 1) v += __shfl_xor_sync(0xffffffffu, v, o);
    return v;
}

// ============================================================================
// Pre-convert: round fp32 -> tf32 (rna) once, in gmem
// ============================================================================
__global__ void cvt_rna_kernel(const float4* __restrict__ s, float4* __restrict__ d, int n4) {
    int i  = blockIdx.x * 256 + threadIdx.x;
    int st = gridDim.x * 256;
    for (; i < n4; i += st) {
        float4 v = s[i];
        v.x = __uint_as_float(tf32u(v.x));
        v.y = __uint_as_float(tf32u(v.y));
        v.z = __uint_as_float(tf32u(v.z));
        v.w = __uint_as_float(tf32u(v.w));
        d[i] = v;
    }
}

// ============================================================================
// Transpose: xT[d][b] = tf32(x[b][d])   (block 32x8, tile 32x32)
// ============================================================================
__global__ __launch_bounds__(256)
void transpose_x(const float* __restrict__ x, float* __restrict__ xT) {
    __shared__ float t[32][33];
    int d0 = blockIdx.x * 32, b0 = blockIdx.y * 32;
    int tx = threadIdx.x, ty = threadIdx.y;
    #pragma unroll
    for (int j = 0; j < 32; j += 8)
        t[ty + j][tx] = x[(size_t)(b0 + ty + j) * D + d0 + tx];
    __syncthreads();
    #pragma unroll
    for (int j = 0; j < 32; j += 8)
        xT[(size_t)(d0 + ty + j) * BATCH + b0 + tx] =
            __uint_as_float(tf32u(t[tx][ty + j]));
}

// ============================================================================
// TN GEMM (mma.sync tf32): C[m][n] = sum_k A[m][k] * B[n][k]
// 128x128 block tile, 4 warps (2x2 of 64x64), BK=16.
// 3-stage cp.async ring, ONE __syncthreads per stage.
// tri=0: m-tile = blockIdx.y, n-tile = blockIdx.x.
// tri=1: blockIdx.x indexes lower-triangle tile pairs (bi >= bj).
// blockIdx.z = split-K chunk; kbase = z*kchunk (applied ONLY via Ab/Bb);
// k0 passed to LOAD is RELATIVE to kbase. C += z*czstride.
// Inputs must be pre-rounded to tf32. ldk = row stride (elements) of A and B.
// ============================================================================
#define RST 3
#define SPITCH 20                       // floats per smem row (pad 16->20)
#define STG_F (128 * SPITCH)            // 2560 floats per tile buffer
#define SMEM_DYN (RST * 2 * STG_F * 4)  // 61440 bytes

__global__ __launch_bounds__(128, 3)
void gemm_mma(const float* __restrict__ A, const float* __restrict__ B,
              float* __restrict__ C, int ldk, int kchunk, long long czstride, int tri) {
    extern __shared__ float sm[];

    const int tid  = threadIdx.x;
    const int warp = tid >> 5, lane = tid & 31;
    const int g = lane >> 2, tg = lane & 3;
    const int wm = (warp >> 1) * 64;
    const int wn = (warp & 1) * 64;

    int bi, bj;
    if (tri) {
        int t = blockIdx.x;
        bi = 0;
        while ((bi + 1) * (bi + 2) / 2 <= t) bi++;
        bj = t - bi * (bi + 1) / 2;
    } else {
        bi = blockIdx.y; bj = blockIdx.x;
    }
    const int m0 = bi * 128, n0 = bj * 128;
    const int kbase = blockIdx.z * kchunk;

    // kbase folded in HERE and only here; LOAD k0 is relative.
    const float* __restrict__ Ab = A + (size_t)m0 * ldk + kbase;
    const float* __restrict__ Bb = B + (size_t)n0 * ldk + kbase;

    float acc[4][8][4];
    #pragma unroll
    for (int i = 0; i < 4; i++)
        #pragma unroll
        for (int j = 0; j < 8; j++)
            #pragma unroll
            for (int q = 0; q < 4; q++) acc[i][j][q] = 0.f;

    const int lr = tid >> 2;          // 0..31
    const int lc = (tid & 3) << 2;    // 0,4,8,12

    auto LOAD = [&](int st, int k0) {
        float* As = sm + (st % RST) * (2 * STG_F);
        float* Bs = As + STG_F;
        #pragma unroll
        for (int i = 0; i < 4; i++) {
            int r = lr + i * 32;
            cpa16(&As[r * SPITCH + lc], Ab + (size_t)r * ldk + k0 + lc);
            cpa16(&Bs[r * SPITCH + lc], Bb + (size_t)r * ldk + k0 + lc);
        }
    };

    auto COMP = [&](int st) {
        const float* As = sm + (st % RST) * (2 * STG_F);
        const float* Bs = As + STG_F;
        #pragma unroll
        for (int ks = 0; ks < 2; ks++) {
            const int kk = ks * 8;
            unsigned a[4][4], b[8][2];
            #pragma unroll
            for (int im = 0; im < 4; im++) {
                int m = wm + im * 16;
                a[im][0] = fu(As[(m + g    ) * SPITCH + kk + tg    ]);
                a[im][1] = fu(As[(m + g + 8) * SPITCH + kk + tg    ]);
                a[im][2] = fu(As[(m + g    ) * SPITCH + kk + tg + 4]);
                a[im][3] = fu(As[(m + g + 8) * SPITCH + kk + tg + 4]);
            }
            #pragma unroll
            for (int jn = 0; jn < 8; jn++) {
                int n = wn + jn * 8;
                b[jn][0] = fu(Bs[(n + g) * SPITCH + kk + tg    ]);
                b[jn][1] = fu(Bs[(n + g) * SPITCH + kk + tg + 4]);
            }
            #pragma unroll
            for (int im = 0; im < 4; im++)
                #pragma unroll
                for (int jn = 0; jn < 8; jn++)
                    mma8(acc[im][jn], a[im][0], a[im][1], a[im][2], a[im][3],
                         b[jn][0], b[jn][1]);
        }
    };

    const int NS = kchunk / 16;
    LOAD(0, 0);  CP_COMMIT();          // relative k0 (bug fix: no kbase here)
    LOAD(1, 16); CP_COMMIT();

    for (int s = 0; s < NS; s++) {
        if (s == NS - 1) { CP_WAIT0(); } else { CP_WAIT1(); }
        __syncthreads();
        // Safe: buffer (s+2)%3 == (s-1)%3; all warps finished COMP(s-1) before this barrier.
        if (s + 2 < NS) { LOAD(s + 2, (s + 2) * 16); CP_COMMIT(); }
        COMP(s);
    }

    float* Cz = C + (size_t)blockIdx.z * czstride;
    #pragma unroll
    for (int im = 0; im < 4; im++) {
        int m = m0 + wm + im * 16 + g;
        #pragma unroll
        for (int jn = 0; jn < 8; jn++) {
            int n = n0 + wn + jn * 8 + tg * 2;
            *(float2*)(Cz + (size_t)m * D + n)       = make_float2(acc[im][jn][0], acc[im][jn][1]);
            *(float2*)(Cz + (size_t)(m + 8) * D + n) = make_float2(acc[im][jn][2], acc[im][jn][3]);
        }
    }
}

// ============================================================================
// Reduce G split-K partials with symmetry mirror; round to tf32.
// Only lower-triangle 128-tiles of g_part are valid; (r,c) in an upper tile
// reads the mirrored element (c,r).
// ============================================================================
__global__ void greduce_kernel() {
    int i = blockIdx.x * 256 + threadIdx.x;        // grid 4096 -> 1M elements
    int r = i >> 10, c = i & 1023;
    size_t src = ((r >> 7) >= (c >> 7)) ? ((size_t)r * D + c) : ((size_t)c * D + r);
    float s = 0.f;
    #pragma unroll
    for (int z = 0; z < GSPLIT; z++) s += g_part[(size_t)z * D * D + src];
    g_G[i] = __uint_as_float(tf32u(s));
}

// ============================================================================
// mean(fast^2, axis=0): two deterministic stages
// ============================================================================
__global__ void msq_stageA() {
    int c  = blockIdx.x * 256 + threadIdx.x;     // grid.x = 4
    int r0 = blockIdx.y * 256;                   // grid.y = 64
    float s0 = 0.f, s1 = 0.f, s2 = 0.f, s3 = 0.f;
    const float* fp = (const float*)g_fast + (size_t)r0 * D + c;
    #pragma unroll 4
    for (int j = 0; j < 256; j += 4) {
        float v0 = fp[(size_t)(j + 0) * D];
        float v1 = fp[(size_t)(j + 1) * D];
        float v2 = fp[(size_t)(j + 2) * D];
        float v3 = fp[(size_t)(j + 3) * D];
        s0 += v0 * v0; s1 += v1 * v1; s2 += v2 * v2; s3 += v3 * v3;
    }
    g_msq_part[blockIdx.y * D + c] = (s0 + s1) + (s2 + s3);
}

__global__ void msq_stageB() {
    int c = blockIdx.x * 256 + threadIdx.x;      // grid.x = 4
    float s = 0.f;
    #pragma unroll
    for (int j = 0; j < 64; j++) s += g_msq_part[j * D + c];
    g_msq[c] = s * (1.0f / (float)BATCH);
}

// ============================================================================
// eff_lr = mean(plasticity) * 0.1
// ============================================================================
__global__ void efflr_kernel(const float* __restrict__ p) {
    int t = threadIdx.x;
    float s = 0.f;
    for (int j = t; j < BATCH; j += 256) s += p[j];
    s = warpSum(s);
    __shared__ float sh[8];
    if ((t & 31) == 0) sh[t >> 5] = s;
    __syncthreads();
    if (t == 0) {
        float tot = 0.f;
        #pragma unroll
        for (int i = 0; i < 8; i++) tot += sh[i];
        g_efflr[0] = tot * (0.1f / (float)BATCH);
    }
}

// ============================================================================
// W_fast_new = W_fast + tanh(hebb/B - msq[o]*W_fast) * eff_lr
// hebb = sum of HSPLIT partial planes in g_part.
// ============================================================================
__global__ __launch_bounds__(256)
void finalize_w(const float* __restrict__ Wf, float* __restrict__ wnew) {
    int o = blockIdx.x;
    float msq = g_msq[o];
    float lr  = g_efflr[0];
    for (int j = threadIdx.x; j < D; j += 256) {
        size_t i = (size_t)o * D + j;
        float h = 0.f;
        #pragma unroll
        for (int z = 0; z < HSPLIT; z++) h += g_part[(size_t)z * D * D + i];
        float wf = Wf[i];
        wnew[i] = wf + tanhf(h * (1.0f / (float)BATCH) - msq * wf) * lr;
    }
}

// ============================================================================
// LayerNorm over combined = slow + alpha*fast; one block per row
// ============================================================================
__global__ __launch_bounds__(256)
void ln_kernel(const float* __restrict__ slow, const float* __restrict__ alpha,
               const float* __restrict__ gamma, const float* __restrict__ beta,
               float* __restrict__ out) {
    int r = blockIdx.x, t = threadIdx.x;
    const float a = alpha[0];
    float4 s4 = ((const float4*)(slow + (size_t)r * D))[t];
    float4 f4 = ((const float4*)((const float*)g_fast + (size_t)r * D))[t];
    float4 v;
    v.x = s4.x + a * f4.x; v.y = s4.y + a * f4.y;
    v.z = s4.z + a * f4.z; v.w = s4.w + a * f4.w;

    float sum = (v.x + v.y) + (v.z + v.w);
    float sq  = (v.x * v.x + v.y * v.y) + (v.z * v.z + v.w * v.w);
    sum = warpSum(sum); sq = warpSum(sq);

    __shared__ float sh[16];
    int w = t >> 5, l = t & 31;
    if (l == 0) { sh[w] = sum; sh[8 + w] = sq; }
    __syncthreads();
    if (t == 0) {
        float s = 0.f, q = 0.f;
        #pragma unroll
        for (int i = 0; i < 8; i++) { s += sh[i]; q += sh[8 + i]; }
        sh[0] = s; sh[8] = q;
    }
    __syncthreads();
    float mu  = sh[0] * (1.0f / (float)D);
    float var = sh[8] * (1.0f / (float)D) - mu * mu;
    float rs  = rsqrtf(var + LN_EPS);

    float4 g4 = ((const float4*)gamma)[t];
    float4 b4 = ((const float4*)beta)[t];
    float4 o4;
    o4.x = (v.x - mu) * rs * g4.x + b4.x;
    o4.y = (v.y - mu) * rs * g4.y + b4.y;
    o4.z = (v.z - mu) * rs * g4.z + b4.z;
    o4.w = (v.w - mu) * rs * g4.w + b4.w;
    ((float4*)(out + (size_t)r * D))[t] = o4;
}

// ============================================================================
extern "C" void kernel_launch(void* const* d_in, const int* in_sizes, int n_in,
                              void* d_out, int out_size) {
    (void)in_sizes; (void)n_in; (void)out_size;
    const float* x     = (const float*)d_in[0];
    const float* plast = (const float*)d_in[1];
    const float* alpha = (const float*)d_in[2];
    const float* Wslow = (const float*)d_in[3];
    const float* Wfast = (const float*)d_in[4];
    const float* gamma = (const float*)d_in[5];
    const float* beta  = (const float*)d_in[6];

    float* out  = (float*)d_out;                 // [16384, 1024]
    float* slow = out  + (size_t)BATCH * D;      // [16384, 1024]
    float* wnew = slow + (size_t)BATCH * D;      // [1024, 1024]

    float* d_xc   = nullptr; cudaGetSymbolAddress((void**)&d_xc,   g_xc);
    float* d_xT   = nullptr; cudaGetSymbolAddress((void**)&d_xT,   g_xT);
    float* d_wsc  = nullptr; cudaGetSymbolAddress((void**)&d_wsc,  g_wsc);
    float* d_wfc  = nullptr; cudaGetSymbolAddress((void**)&d_wfc,  g_wfc);
    float* d_fast = nullptr; cudaGetSymbolAddress((void**)&d_fast, g_fast);
    float* d_part = nullptr; cudaGetSymbolAddress((void**)&d_part, g_part);
    float* d_G    = nullptr; cudaGetSymbolAddress((void**)&d_G,    g_G);

    static bool attr_set = false;
    if (!attr_set) {
        cudaFuncSetAttribute(gemm_mma, cudaFuncAttributeMaxDynamicSharedMemorySize, SMEM_DYN);
        attr_set = true;
    }

    cvt_rna_kernel<<<1024, 256>>>((const float4*)x,     (float4*)d_xc,  BATCH * D / 4);
    cvt_rna_kernel<<<256,  256>>>((const float4*)Wslow, (float4*)d_wsc, D * D / 4);
    cvt_rna_kernel<<<256,  256>>>((const float4*)Wfast, (float4*)d_wfc, D * D / 4);
    transpose_x<<<dim3(D / 32, BATCH / 32), dim3(32, 8)>>>(x, d_xT);

    // slow = x @ Wslow^T ; fast = x @ Wfast^T   (grid: n-tiles x m-tiles)
    gemm_mma<<<dim3(8, 128), 128, SMEM_DYN>>>(d_xc, d_wsc, slow,   D, D, 0, 0);
    gemm_mma<<<dim3(8, 128), 128, SMEM_DYN>>>(d_xc, d_wfc, d_fast, D, D, 0, 0);

    msq_stageA<<<dim3(4, 64), 256>>>();
    msq_stageB<<<4, 256>>>();
    efflr_kernel<<<1, 256>>>(plast);

    // G = x^T x : lower-triangle tiles only (36 pairs), split-K over batch
    gemm_mma<<<dim3(36, 1, GSPLIT), 128, SMEM_DYN>>>(d_xT, d_xT, d_part,
                                                     BATCH, BATCH / GSPLIT,
                                                     (long long)D * D, 1);
    greduce_kernel<<<4096, 256>>>();

    // hebb = Wf @ G (G symmetric -> B rows are G rows), split-K 4 into g_part
    gemm_mma<<<dim3(8, 8, HSPLIT), 128, SMEM_DYN>>>(d_wfc, d_G, d_part,
                                                    D, D / HSPLIT,
                                                    (long long)D * D, 0);

    finalize_w<<<1024, 256>>>(Wfast, wnew);
    ln_kernel<<<16384, 256>>>(slow, alpha, gamma, beta, out);
}

// round 12
// speedup vs baseline: 1.1884x; 1.1884x over previous
#include <cuda_runtime.h>
#include <cstdint>

#define BATCH 16384
#define D     1024
#define LN_EPS 1e-5f
#define GSPLIT 8          // split-K for G = x^T x
#define HSPLIT 4          // split-K for hebb = Wf * G

// ---------------- scratch (static device globals; no runtime alloc) ----------
__device__ __align__(16) float g_xc  [(size_t)BATCH * D];     // x rounded to tf32
__device__ __align__(16) float g_wsc [(size_t)D * D];         // W_slow rounded
__device__ __align__(16) float g_wfc [(size_t)D * D];         // W_fast rounded
__device__ __align__(16) float g_fast[(size_t)BATCH * D];     // fast, fp32
__device__ __align__(16) float g_part[(size_t)GSPLIT * D * D];// split-K partials (G, then hebb)
__device__ __align__(16) float g_G   [(size_t)D * D];         // G = x^T x (full, tf32)
__device__ float g_msq_part[64 * D];
__device__ float g_msq[D];
__device__ float g_efflr[1];

// ---------------- helpers ----------------------------------------------------
__device__ __forceinline__ unsigned tf32u(float x) {
    unsigned r;
    asm("cvt.rna.tf32.f32 %0, %1;" : "=r"(r) : "f"(x));
    return r;
}
__device__ __forceinline__ unsigned fu(float x) { return __float_as_uint(x); }

__device__ __forceinline__ void mma8(float c[4],
                                     unsigned a0, unsigned a1, unsigned a2, unsigned a3,
                                     unsigned b0, unsigned b1) {
    asm volatile(
        "mma.sync.aligned.m16n8k8.row.col.f32.tf32.tf32.f32 "
        "{%0,%1,%2,%3}, {%4,%5,%6,%7}, {%8,%9}, {%0,%1,%2,%3};\n"
        : "+f"(c[0]), "+f"(c[1]), "+f"(c[2]), "+f"(c[3])
        : "r"(a0), "r"(a1), "r"(a2), "r"(a3), "r"(b0), "r"(b1));
}

__device__ __forceinline__ void cpa16(void* dst, const void* src) {
    unsigned sd = (unsigned)__cvta_generic_to_shared(dst);
    asm volatile("cp.async.cg.shared.global [%0], [%1], 16;\n" :: "r"(sd), "l"(src));
}
#define CP_COMMIT() asm volatile("cp.async.commit_group;\n" ::: "memory")
#define CP_WAIT0()  asm volatile("cp.async.wait_group 0;\n" ::: "memory")
#define CP_WAIT1()  asm volatile("cp.async.wait_group 1;\n" ::: "memory")

__device__ __forceinline__ float warpSum(float v) {
    #pragma unroll
    for (int o = 16; o > 0; o >>= 1) v += __shfl_xor_sync(0xffffffffu, v, o);
    return v;
}

// ============================================================================
// Pre-convert: round fp32 -> tf32 (rna) once, in gmem
// ============================================================================
__global__ void cvt_rna_kernel(const float4* __restrict__ s, float4* __restrict__ d, int n4) {
    int i  = blockIdx.x * 256 + threadIdx.x;
    int st = gridDim.x * 256;
    for (; i < n4; i += st) {
        float4 v = s[i];
        v.x = __uint_as_float(tf32u(v.x));
        v.y = __uint_as_float(tf32u(v.y));
        v.z = __uint_as_float(tf32u(v.z));
        v.w = __uint_as_float(tf32u(v.w));
        d[i] = v;
    }
}

// ============================================================================
// TN GEMM (mma.sync tf32): C[m][n] = sum_k A[m][k] * B[n][k]
// 128x128 block tile, 4 warps (2x2 of 64x64), BK=16, 3-stage cp.async ring,
// one __syncthreads per stage. __launch_bounds__(128,2): high reg budget so
// ptxas double-buffers the two ks fragment sets (LDS of ks1 overlaps MMA ks0).
// blockIdx.z = split-K chunk (kbase folded into Ab/Bb ONLY; LOAD k0 relative).
// ============================================================================
#define RST 3
#define SPITCH 20                       // floats per smem row (pad 16->20)
#define STG_F (128 * SPITCH)            // 2560 floats per tile buffer
#define SMEM_DYN (RST * 2 * STG_F * 4)  // 61440 bytes

__global__ __launch_bounds__(128, 2)
void gemm_mma(const float* __restrict__ A, const float* __restrict__ B,
              float* __restrict__ C, int ldk, int kchunk, long long czstride) {
    extern __shared__ float sm[];

    const int tid  = threadIdx.x;
    const int warp = tid >> 5, lane = tid & 31;
    const int g = lane >> 2, tg = lane & 3;
    const int wm = (warp >> 1) * 64;
    const int wn = (warp & 1) * 64;

    const int m0 = blockIdx.y * 128, n0 = blockIdx.x * 128;
    const int kbase = blockIdx.z * kchunk;

    const float* __restrict__ Ab = A + (size_t)m0 * ldk + kbase;
    const float* __restrict__ Bb = B + (size_t)n0 * ldk + kbase;

    float acc[4][8][4];
    #pragma unroll
    for (int i = 0; i < 4; i++)
        #pragma unroll
        for (int j = 0; j < 8; j++)
            #pragma unroll
            for (int q = 0; q < 4; q++) acc[i][j][q] = 0.f;

    const int lr = tid >> 2;          // 0..31
    const int lc = (tid & 3) << 2;    // 0,4,8,12

    auto LOAD = [&](int st, int k0) {
        float* As = sm + (st % RST) * (2 * STG_F);
        float* Bs = As + STG_F;
        #pragma unroll
        for (int i = 0; i < 4; i++) {
            int r = lr + i * 32;
            cpa16(&As[r * SPITCH + lc], Ab + (size_t)r * ldk + k0 + lc);
            cpa16(&Bs[r * SPITCH + lc], Bb + (size_t)r * ldk + k0 + lc);
        }
    };

    auto LDFRAG = [&](const float* As, const float* Bs, int kk,
                      unsigned a[4][4], unsigned b[8][2]) {
        #pragma unroll
        for (int im = 0; im < 4; im++) {
            int m = wm + im * 16;
            a[im][0] = fu(As[(m + g    ) * SPITCH + kk + tg    ]);
            a[im][1] = fu(As[(m + g + 8) * SPITCH + kk + tg    ]);
            a[im][2] = fu(As[(m + g    ) * SPITCH + kk + tg + 4]);
            a[im][3] = fu(As[(m + g + 8) * SPITCH + kk + tg + 4]);
        }
        #pragma unroll
        for (int jn = 0; jn < 8; jn++) {
            int n = wn + jn * 8;
            b[jn][0] = fu(Bs[(n + g) * SPITCH + kk + tg    ]);
            b[jn][1] = fu(Bs[(n + g) * SPITCH + kk + tg + 4]);
        }
    };

    auto MMAS = [&](unsigned a[4][4], unsigned b[8][2]) {
        #pragma unroll
        for (int im = 0; im < 4; im++)
            #pragma unroll
            for (int jn = 0; jn < 8; jn++)
                mma8(acc[im][jn], a[im][0], a[im][1], a[im][2], a[im][3],
                     b[jn][0], b[jn][1]);
    };

    const int NS = kchunk / 16;
    LOAD(0, 0);  CP_COMMIT();
    LOAD(1, 16); CP_COMMIT();

    for (int s = 0; s < NS; s++) {
        if (s == NS - 1) { CP_WAIT0(); } else { CP_WAIT1(); }
        __syncthreads();
        if (s + 2 < NS) { LOAD(s + 2, (s + 2) * 16); CP_COMMIT(); }
        const float* As = sm + (s % RST) * (2 * STG_F);
        const float* Bs = As + STG_F;
        unsigned aA[4][4], bA[8][2], aB[4][4], bB[8][2];
        LDFRAG(As, Bs, 0, aA, bA);
        LDFRAG(As, Bs, 8, aB, bB);     // independent of MMAS(aA,bA): overlaps
        MMAS(aA, bA);
        MMAS(aB, bB);
    }

    float* Cz = C + (size_t)blockIdx.z * czstride;
    #pragma unroll
    for (int im = 0; im < 4; im++) {
        int m = m0 + wm + im * 16 + g;
        #pragma unroll
        for (int jn = 0; jn < 8; jn++) {
            int n = n0 + wn + jn * 8 + tg * 2;
            *(float2*)(Cz + (size_t)m * D + n)       = make_float2(acc[im][jn][0], acc[im][jn][1]);
            *(float2*)(Cz + (size_t)(m + 8) * D + n) = make_float2(acc[im][jn][2], acc[im][jn][3]);
        }
    }
}

// ============================================================================
// G = x^T x, MN-major loads (no transpose needed): reads x rows [k][*] directly.
// partial[z][m][n] = sum_{k in chunk z} x[k][m] * x[k][n]
// 128x128 tile, 4 warps (2x2 of 64x64), BK=16, 3-stage ring, frag dbl-buffer.
// blockIdx.x indexes lower-triangle tile pairs (bi >= bj); 36 pairs.
// ============================================================================
#define GPITCH 136
#define GSTG_F (16 * GPITCH)            // 2176 floats per tile buffer
#define GSMEM_DYN (RST * 2 * GSTG_F * 4) // 52224 bytes

__global__ __launch_bounds__(128, 2)
void gemm_g(const float* __restrict__ X) {
    extern __shared__ float sm[];

    const int tid  = threadIdx.x;
    const int warp = tid >> 5, lane = tid & 31;
    const int g = lane >> 2, tg = lane & 3;
    const int wm = (warp >> 1) * 64;
    const int wn = (warp & 1) * 64;

    int t = blockIdx.x;
    int bi = 0;
    while ((bi + 1) * (bi + 2) / 2 <= t) bi++;
    int bj = t - bi * (bi + 1) / 2;
    const int m0 = bi * 128, n0 = bj * 128;
    const int kbase = blockIdx.z * (BATCH / GSPLIT);   // 2048 per split

    float acc[4][8][4];
    #pragma unroll
    for (int i = 0; i < 4; i++)
        #pragma unroll
        for (int j = 0; j < 8; j++)
            #pragma unroll
            for (int q = 0; q < 4; q++) acc[i][j][q] = 0.f;

    const int lr = tid >> 3;          // 0..15 (k row)
    const int lc = (tid & 7) << 2;    // 0..28

    auto LOAD = [&](int st, int k0) {
        float* As = sm + (st % RST) * (2 * GSTG_F);
        float* Bs = As + GSTG_F;
        const float* xr = X + (size_t)(kbase + k0 + lr) * D;
        #pragma unroll
        for (int i = 0; i < 4; i++) {
            int c = lc + 32 * i;
            cpa16(&As[lr * GPITCH + c], xr + m0 + c);
            cpa16(&Bs[lr * GPITCH + c], xr + n0 + c);
        }
    };

    auto LDFRAG = [&](const float* As, const float* Bs, int kk,
                      unsigned a[4][4], unsigned b[8][2]) {
        #pragma unroll
        for (int im = 0; im < 4; im++) {
            int m = wm + im * 16;
            a[im][0] = fu(As[(kk + tg    ) * GPITCH + m + g    ]);
            a[im][1] = fu(As[(kk + tg    ) * GPITCH + m + g + 8]);
            a[im][2] = fu(As[(kk + tg + 4) * GPITCH + m + g    ]);
            a[im][3] = fu(As[(kk + tg + 4) * GPITCH + m + g + 8]);
        }
        #pragma unroll
        for (int jn = 0; jn < 8; jn++) {
            int n = wn + jn * 8;
            b[jn][0] = fu(Bs[(kk + tg    ) * GPITCH + n + g]);
            b[jn][1] = fu(Bs[(kk + tg + 4) * GPITCH + n + g]);
        }
    };

    auto MMAS = [&](unsigned a[4][4], unsigned b[8][2]) {
        #pragma unroll
        for (int im = 0; im < 4; im++)
            #pragma unroll
            for (int jn = 0; jn < 8; jn++)
                mma8(acc[im][jn], a[im][0], a[im][1], a[im][2], a[im][3],
                     b[jn][0], b[jn][1]);
    };

    const int NS = (BATCH / GSPLIT) / 16;  // 128
    LOAD(0, 0);  CP_COMMIT();
    LOAD(1, 16); CP_COMMIT();

    for (int s = 0; s < NS; s++) {
        if (s == NS - 1) { CP_WAIT0(); } else { CP_WAIT1(); }
        __syncthreads();
        if (s + 2 < NS) { LOAD(s + 2, (s + 2) * 16); CP_COMMIT(); }
        const float* As = sm + (s % RST) * (2 * GSTG_F);
        const float* Bs = As + GSTG_F;
        unsigned aA[4][4], bA[8][2], aB[4][4], bB[8][2];
        LDFRAG(As, Bs, 0, aA, bA);
        LDFRAG(As, Bs, 8, aB, bB);
        MMAS(aA, bA);
        MMAS(aB, bB);
    }

    float* Cp = (float*)g_part + (size_t)blockIdx.z * D * D;
    #pragma unroll
    for (int im = 0; im < 4; im++) {
        int m = m0 + wm + im * 16 + g;
        #pragma unroll
        for (int jn = 0; jn < 8; jn++) {
            int n = n0 + wn + jn * 8 + tg * 2;
            *(float2*)(Cp + (size_t)m * D + n)       = make_float2(acc[im][jn][0], acc[im][jn][1]);
            *(float2*)(Cp + (size_t)(m + 8) * D + n) = make_float2(acc[im][jn][2], acc[im][jn][3]);
        }
    }
}

// ============================================================================
// Reduce G split-K partials with symmetry mirror; round to tf32.
// ============================================================================
__global__ void greduce_kernel() {
    int i = blockIdx.x * 256 + threadIdx.x;        // grid 4096 -> 1M elements
    int r = i >> 10, c = i & 1023;
    size_t src = ((r >> 7) >= (c >> 7)) ? ((size_t)r * D + c) : ((size_t)c * D + r);
    float s = 0.f;
    #pragma unroll
    for (int z = 0; z < GSPLIT; z++) s += g_part[(size_t)z * D * D + src];
    g_G[i] = __uint_as_float(tf32u(s));
}

// ============================================================================
// mean(fast^2, axis=0): two deterministic stages
// ============================================================================
__global__ void msq_stageA() {
    int c  = blockIdx.x * 256 + threadIdx.x;     // grid.x = 4
    int r0 = blockIdx.y * 256;                   // grid.y = 64
    float s0 = 0.f, s1 = 0.f, s2 = 0.f, s3 = 0.f;
    const float* fp = (const float*)g_fast + (size_t)r0 * D + c;
    #pragma unroll 4
    for (int j = 0; j < 256; j += 4) {
        float v0 = fp[(size_t)(j + 0) * D];
        float v1 = fp[(size_t)(j + 1) * D];
        float v2 = fp[(size_t)(j + 2) * D];
        float v3 = fp[(size_t)(j + 3) * D];
        s0 += v0 * v0; s1 += v1 * v1; s2 += v2 * v2; s3 += v3 * v3;
    }
    g_msq_part[blockIdx.y * D + c] = (s0 + s1) + (s2 + s3);
}

__global__ void msq_stageB() {
    int c = blockIdx.x * 256 + threadIdx.x;      // grid.x = 4
    float s = 0.f;
    #pragma unroll
    for (int j = 0; j < 64; j++) s += g_msq_part[j * D + c];
    g_msq[c] = s * (1.0f / (float)BATCH);
}

// ============================================================================
// eff_lr = mean(plasticity) * 0.1
// ============================================================================
__global__ void efflr_kernel(const float* __restrict__ p) {
    int t = threadIdx.x;
    float s = 0.f;
    for (int j = t; j < BATCH; j += 256) s += p[j];
    s = warpSum(s);
    __shared__ float sh[8];
    if ((t & 31) == 0) sh[t >> 5] = s;
    __syncthreads();
    if (t == 0) {
        float tot = 0.f;
        #pragma unroll
        for (int i = 0; i < 8; i++) tot += sh[i];
        g_efflr[0] = tot * (0.1f / (float)BATCH);
    }
}

// ============================================================================
// W_fast_new = W_fast + tanh(hebb/B - msq[o]*W_fast) * eff_lr
// ============================================================================
__global__ __launch_bounds__(256)
void finalize_w(const float* __restrict__ Wf, float* __restrict__ wnew) {
    int o = blockIdx.x;
    float msq = g_msq[o];
    float lr  = g_efflr[0];
    for (int j = threadIdx.x; j < D; j += 256) {
        size_t i = (size_t)o * D + j;
        float h = 0.f;
        #pragma unroll
        for (int z = 0; z < HSPLIT; z++) h += g_part[(size_t)z * D * D + i];
        float wf = Wf[i];
        wnew[i] = wf + tanhf(h * (1.0f / (float)BATCH) - msq * wf) * lr;
    }
}

// ============================================================================
// LayerNorm over combined = slow + alpha*fast; one block per row
// ============================================================================
__global__ __launch_bounds__(256)
void ln_kernel(const float* __restrict__ slow, const float* __restrict__ alpha,
               const float* __restrict__ gamma, const float* __restrict__ beta,
               float* __restrict__ out) {
    int r = blockIdx.x, t = threadIdx.x;
    const float a = alpha[0];
    float4 s4 = ((const float4*)(slow + (size_t)r * D))[t];
    float4 f4 = ((const float4*)((const float*)g_fast + (size_t)r * D))[t];
    float4 v;
    v.x = s4.x + a * f4.x; v.y = s4.y + a * f4.y;
    v.z = s4.z + a * f4.z; v.w = s4.w + a * f4.w;

    float sum = (v.x + v.y) + (v.z + v.w);
    float sq  = (v.x * v.x + v.y * v.y) + (v.z * v.z + v.w * v.w);
    sum = warpSum(sum); sq = warpSum(sq);

    __shared__ float sh[16];
    int w = t >> 5, l = t & 31;
    if (l == 0) { sh[w] = sum; sh[8 + w] = sq; }
    __syncthreads();
    if (t == 0) {
        float s = 0.f, q = 0.f;
        #pragma unroll
        for (int i = 0; i < 8; i++) { s += sh[i]; q += sh[8 + i]; }
        sh[0] = s; sh[8] = q;
    }
    __syncthreads();
    float mu  = sh[0] * (1.0f / (float)D);
    float var = sh[8] * (1.0f / (float)D) - mu * mu;
    float rs  = rsqrtf(var + LN_EPS);

    float4 g4 = ((const float4*)gamma)[t];
    float4 b4 = ((const float4*)beta)[t];
    float4 o4;
    o4.x = (v.x - mu) * rs * g4.x + b4.x;
    o4.y = (v.y - mu) * rs * g4.y + b4.y;
    o4.z = (v.z - mu) * rs * g4.z + b4.z;
    o4.w = (v.w - mu) * rs * g4.w + b4.w;
    ((float4*)(out + (size_t)r * D))[t] = o4;
}

// ============================================================================
extern "C" void kernel_launch(void* const* d_in, const int* in_sizes, int n_in,
                              void* d_out, int out_size) {
    (void)in_sizes; (void)n_in; (void)out_size;
    const float* x     = (const float*)d_in[0];
    const float* plast = (const float*)d_in[1];
    const float* alpha = (const float*)d_in[2];
    const float* Wslow = (const float*)d_in[3];
    const float* Wfast = (const float*)d_in[4];
    const float* gamma = (const float*)d_in[5];
    const float* beta  = (const float*)d_in[6];

    float* out  = (float*)d_out;                 // [16384, 1024]
    float* slow = out  + (size_t)BATCH * D;      // [16384, 1024]
    float* wnew = slow + (size_t)BATCH * D;      // [1024, 1024]

    float* d_xc   = nullptr; cudaGetSymbolAddress((void**)&d_xc,   g_xc);
    float* d_wsc  = nullptr; cudaGetSymbolAddress((void**)&d_wsc,  g_wsc);
    float* d_wfc  = nullptr; cudaGetSymbolAddress((void**)&d_wfc,  g_wfc);
    float* d_fast = nullptr; cudaGetSymbolAddress((void**)&d_fast, g_fast);
    float* d_part = nullptr; cudaGetSymbolAddress((void**)&d_part, g_part);
    float* d_G    = nullptr; cudaGetSymbolAddress((void**)&d_G,    g_G);

    static bool attr_set = false;
    if (!attr_set) {
        cudaFuncSetAttribute(gemm_mma, cudaFuncAttributeMaxDynamicSharedMemorySize, SMEM_DYN);
        cudaFuncSetAttribute(gemm_g,   cudaFuncAttributeMaxDynamicSharedMemorySize, GSMEM_DYN);
        attr_set = true;
    }

    cvt_rna_kernel<<<1024, 256>>>((const float4*)x,     (float4*)d_xc,  BATCH * D / 4);
    cvt_rna_kernel<<<256,  256>>>((const float4*)Wslow, (float4*)d_wsc, D * D / 4);
    cvt_rna_kernel<<<256,  256>>>((const float4*)Wfast, (float4*)d_wfc, D * D / 4);

    // slow = x @ Wslow^T ; fast = x @ Wfast^T   (grid: n-tiles x m-tiles)
    gemm_mma<<<dim3(8, 128), 128, SMEM_DYN>>>(d_xc, d_wsc, slow,   D, D, 0);
    gemm_mma<<<dim3(8, 128), 128, SMEM_DYN>>>(d_xc, d_wfc, d_fast, D, D, 0);

    msq_stageA<<<dim3(4, 64), 256>>>();
    msq_stageB<<<4, 256>>>();
    efflr_kernel<<<1, 256>>>(plast);

    // G = x^T x : lower-triangle tiles only (36 pairs), split-K over batch,
    // MN-major loads straight from g_xc (no transpose kernel)
    gemm_g<<<dim3(36, 1, GSPLIT), 128, GSMEM_DYN>>>(d_xc);
    greduce_kernel<<<4096, 256>>>();

    // hebb = Wf @ G (G symmetric -> B rows are G rows), split-K 4 into g_part
    gemm_mma<<<dim3(8, 8, HSPLIT), 128, SMEM_DYN>>>(d_wfc, d_G, d_part,
                                                    D, D / HSPLIT,
                                                    (long long)D * D);

    finalize_w<<<1024, 256>>>(Wfast, wnew);
    ln_kernel<<<16384, 256>>>(slow, alpha, gamma, beta, out);
}